// round 11
// baseline (speedup 1.0000x reference)
#include <cuda_runtime.h>

// ---------------------------------------------------------------------------
// BatchedGAT: B=8, N=512, IN=256, H=4, C=32, OUT=128, LeakyReLU slope 0.2
// K1: projections xl = x@W_l + b_l, xr = x@W_r + b_r  -> [B,H,N,C]
// K2: e_ij = v_j + sum_c 0.4*att_c*|xr_ic + xl_jc|  (linear xr part cancels
//     in softmax; xl part = v_j), masked softmax, out = (p@xl)/rowsum + bias.
//     Mask built in-kernel from adj (thread j loads adj[b][j][i0..i0+31]).
//     512 threads, 32-row i-tiles, xl in smem (R6 structure).
// ---------------------------------------------------------------------------

#define Bn 8
#define Nn 512
#define INDIM 256
#define Hh 4
#define Cc 32
#define ODIM 128

typedef unsigned long long u64;

__device__ float g_xl[Bn * Hh * Nn * Cc];        // [b][h][j][c]
__device__ float g_xr[Bn * Hh * Nn * Cc];        // [b][h][i][c]

__device__ __forceinline__ u64 f2add(u64 a, u64 b) {
    u64 r; asm("add.rn.f32x2 %0, %1, %2;" : "=l"(r) : "l"(a), "l"(b)); return r;
}
__device__ __forceinline__ u64 f2fma(u64 a, u64 b, u64 c) {
    u64 r; asm("fma.rn.f32x2 %0, %1, %2, %3;" : "=l"(r) : "l"(a), "l"(b), "l"(c)); return r;
}
__device__ __forceinline__ float2 f2unpack(u64 v) {
    float2 r; asm("mov.b64 {%0, %1}, %2;" : "=f"(r.x), "=f"(r.y) : "l"(v)); return r;
}

#define ABSMASK 0x7FFFFFFF7FFFFFFFULL
#define NEGINF  __int_as_float(0xff800000)

// ---------------------------------------------------------------------------
// Kernel 1: tiled SIMT GEMM. M=4096, K=256, Ncols=256 (xl | xr)
// ---------------------------------------------------------------------------
#define BM 64
#define BN 64
#define BK 16

__global__ void __launch_bounds__(256) proj_kernel(
    const float* __restrict__ x,
    const float* __restrict__ Wl, const float* __restrict__ bl,
    const float* __restrict__ Wr, const float* __restrict__ br)
{
    __shared__ float As[BK][BM + 4];
    __shared__ float Bs[BK][BN + 4];

    const int tid = threadIdx.x;
    const int m0 = blockIdx.x * BM;
    const int n0 = blockIdx.y * BN;
    const float* W  = (n0 < 128) ? Wl : Wr;
    const float* bb = (n0 < 128) ? bl : br;
    float* dstg     = (n0 < 128) ? g_xl : g_xr;
    const int wcol0 = n0 & 127;

    const int ty = tid >> 4;
    const int tx = tid & 15;
    const int ar  = tid >> 2;
    const int ak4 = (tid & 3) << 2;
    const int bk  = tid >> 4;
    const int bn4 = (tid & 15) << 2;

    float acc[4][4];
    #pragma unroll
    for (int r = 0; r < 4; r++)
        #pragma unroll
        for (int c = 0; c < 4; c++) acc[r][c] = 0.f;

    for (int k0 = 0; k0 < INDIM; k0 += BK) {
        float4 av = *(const float4*)&x[(m0 + ar) * INDIM + k0 + ak4];
        As[ak4 + 0][ar] = av.x;
        As[ak4 + 1][ar] = av.y;
        As[ak4 + 2][ar] = av.z;
        As[ak4 + 3][ar] = av.w;
        float4 bv = *(const float4*)&W[(k0 + bk) * ODIM + wcol0 + bn4];
        *(float4*)&Bs[bk][bn4] = bv;
        __syncthreads();

        #pragma unroll
        for (int kk = 0; kk < BK; kk++) {
            float4 a = *(const float4*)&As[kk][ty * 4];
            float4 b = *(const float4*)&Bs[kk][tx * 4];
            float aa[4] = {a.x, a.y, a.z, a.w};
            float bbv[4] = {b.x, b.y, b.z, b.w};
            #pragma unroll
            for (int r = 0; r < 4; r++)
                #pragma unroll
                for (int c = 0; c < 4; c++) acc[r][c] += aa[r] * bbv[c];
        }
        __syncthreads();
    }

    const int oc0 = n0 + tx * 4;
    const int h   = (oc0 & 127) >> 5;
    const int ch  = oc0 & 31;
    float4 bias4;
    bias4.x = bb[wcol0 + tx * 4 + 0];
    bias4.y = bb[wcol0 + tx * 4 + 1];
    bias4.z = bb[wcol0 + tx * 4 + 2];
    bias4.w = bb[wcol0 + tx * 4 + 3];

    #pragma unroll
    for (int r = 0; r < 4; r++) {
        const int m = m0 + ty * 4 + r;
        const int bidx = m >> 9;
        const int n = m & 511;
        float4 v;
        v.x = acc[r][0] + bias4.x;
        v.y = acc[r][1] + bias4.y;
        v.z = acc[r][2] + bias4.z;
        v.w = acc[r][3] + bias4.w;
        *(float4*)&dstg[(((bidx * Hh + h) * Nn) + n) * Cc + ch] = v;
    }
}

// ---------------------------------------------------------------------------
// Kernel 2: attention. grid (16, 4, 8), 512 threads. Mask built from adj.
// ---------------------------------------------------------------------------
#define XL_ST 36
#define ES_ST 516
#define SM_XL   0                          // 512*36 = 18432
#define SM_XR   (SM_XL + Nn * XL_ST)       // 1024
#define SM_ES   (SM_XR + 1024)             // 32*516 = 16512
#define SM_W4   (SM_ES + 32 * ES_ST)       // 32
#define SM_W6   (SM_W4 + 32)               // 32
#define SM_RINV (SM_W6 + 32)               // 32
#define SM_PS   (SM_RINV + 32)             // 2 halves * 32 rows * 32 ch = 2048
#define SM_FLOATS (SM_PS + 2048)
#define SMEM_BYTES (SM_FLOATS * 4)         // 152448 bytes

__global__ void __launch_bounds__(512) gat_kernel(
    const int* __restrict__ adj,
    const float* __restrict__ att,
    const float* __restrict__ bias,
    float* __restrict__ out)
{
    extern __shared__ float sm[];
    float* xl_s = sm + SM_XL;
    float* xr_s = sm + SM_XR;
    float* e_s  = sm + SM_ES;
    float* w4_s = sm + SM_W4;
    float* w6_s = sm + SM_W6;
    float* rinv_s = sm + SM_RINV;
    float* ps_s = sm + SM_PS;

    const int tid = threadIdx.x;
    const int w = tid >> 5;
    const int l = tid & 31;
    const int b  = blockIdx.z;
    const int h  = blockIdx.y;
    const int bx = blockIdx.x;
    const int i0 = bx * 32;

    const float* xl = g_xl + ((b * Hh + h) * Nn) * Cc;
    const float* xr = g_xr + ((b * Hh + h) * Nn + i0) * Cc;

    // ---- in-register mask build: thread j = tid owns adj[b][j][i0..i0+31] ----
    unsigned m;
    {
        const int4* arow = (const int4*)(adj + (b * Nn + tid) * Nn + i0);
        int4 a4[8];
        #pragma unroll
        for (int k = 0; k < 8; k++) a4[k] = arow[k];       // MLP 8, coalesced
        m = 0u;
        #pragma unroll
        for (int k = 0; k < 8; k++) {
            m |= (unsigned)(a4[k].x != 0) << (4 * k + 0);
            m |= (unsigned)(a4[k].y != 0) << (4 * k + 1);
            m |= (unsigned)(a4[k].z != 0) << (4 * k + 2);
            m |= (unsigned)(a4[k].w != 0) << (4 * k + 3);
        }
        const int d = tid - i0;
        if ((unsigned)d < 32u) m |= 1u << d;               // forced diagonal
    }

    // ---- tile loads ----
    if (tid < 32) {
        float a = att[h * Cc + tid];
        w4_s[tid] = 0.4f * a;
        w6_s[tid] = 0.6f * a;
    }
    #pragma unroll
    for (int q8 = 0; q8 < 8; q8++) {
        int idx = q8 * 512 + tid;          // 4096 float4
        int j = idx >> 3, cc = (idx & 7) << 2;
        *(float4*)&xl_s[j * XL_ST + cc] = *(const float4*)&xl[j * Cc + cc];
    }
    if (tid < 256) {
        int j = tid >> 3, cc = (tid & 7) << 2;
        *(float4*)&xr_s[j * Cc + cc] = *(const float4*)&xr[j * Cc + cc];
    }
    __syncthreads();

    // ---- Phase 1: e scores, j-sliced. Warp w owns j = 32w + l = tid ----
    {
        const int j = tid;
        u64 q[16];
        {
            const ulonglong2* qp = (const ulonglong2*)&xl_s[j * XL_ST];
            #pragma unroll
            for (int k = 0; k < 8; k++) { ulonglong2 t = qp[k]; q[2*k] = t.x; q[2*k+1] = t.y; }
        }
        u64 w4r[16];
        {
            const ulonglong2* wp = (const ulonglong2*)w4_s;
            #pragma unroll
            for (int k = 0; k < 8; k++) { ulonglong2 t = wp[k]; w4r[2*k] = t.x; w4r[2*k+1] = t.y; }
        }
        float v;
        {
            const u64* w6p = (const u64*)w6_s;
            u64 va = 0ull, vb = 0ull;
            #pragma unroll
            for (int k = 0; k < 16; k += 2) {
                va = f2fma(w6p[k],   q[k],   va);
                vb = f2fma(w6p[k+1], q[k+1], vb);
            }
            float2 f = f2unpack(f2add(va, vb));
            v = f.x + f.y;
        }
        float* erow = &e_s[j];

        #pragma unroll 4
        for (int i = 0; i < 32; i++) {
            const ulonglong2* xp = (const ulonglong2*)&xr_s[i * Cc];
            u64 a0 = 0ull, a1 = 0ull, a2 = 0ull, a3 = 0ull;
            #pragma unroll
            for (int k = 0; k < 8; k += 2) {
                ulonglong2 t0 = xp[k], t1 = xp[k+1];
                u64 s0 = f2add(t0.x, q[2*k])   & ABSMASK;
                u64 s1 = f2add(t0.y, q[2*k+1]) & ABSMASK;
                u64 s2 = f2add(t1.x, q[2*k+2]) & ABSMASK;
                u64 s3 = f2add(t1.y, q[2*k+3]) & ABSMASK;
                a0 = f2fma(w4r[2*k],   s0, a0);
                a1 = f2fma(w4r[2*k+1], s1, a1);
                a2 = f2fma(w4r[2*k+2], s2, a2);
                a3 = f2fma(w4r[2*k+3], s3, a3);
            }
            float2 f = f2unpack(f2add(f2add(a0, a1), f2add(a2, a3)));
            float e = f.x + f.y + v;
            e = ((m >> i) & 1u) ? e : NEGINF;
            erow[i * ES_ST] = e;
        }
    }
    __syncthreads();

    // ---- Phase 2: masked softmax. Warp w owns rows 2w, 2w+1 ----
    #pragma unroll
    for (int rs = 0; rs < 2; rs++) {
        const int r = 2 * w + rs;
        float vals[16];
        #pragma unroll
        for (int p4 = 0; p4 < 4; p4++) {
            float4 f = *(float4*)&e_s[r * ES_ST + p4 * 128 + l * 4];
            vals[p4*4]   = f.x; vals[p4*4+1] = f.y;
            vals[p4*4+2] = f.z; vals[p4*4+3] = f.w;
        }
        float mx = vals[0];
        #pragma unroll
        for (int k = 1; k < 16; k++) mx = fmaxf(mx, vals[k]);
        #pragma unroll
        for (int off = 16; off > 0; off >>= 1)
            mx = fmaxf(mx, __shfl_xor_sync(0xffffffffu, mx, off));
        float sum = 0.f;
        #pragma unroll
        for (int k = 0; k < 16; k++) {
            float p = __expf(vals[k] - mx);
            vals[k] = p;
            sum += p;
        }
        #pragma unroll
        for (int off = 16; off > 0; off >>= 1)
            sum += __shfl_xor_sync(0xffffffffu, sum, off);
        #pragma unroll
        for (int p4 = 0; p4 < 4; p4++) {
            *(float4*)&e_s[r * ES_ST + p4 * 128 + l * 4] =
                make_float4(vals[p4*4], vals[p4*4+1], vals[p4*4+2], vals[p4*4+3]);
        }
        if (l == 0) rinv_s[r] = 1.f / sum;
    }
    __syncthreads();

    // ---- Phase D: warp w -> rows 4*(w&7)..+3, j-half (w>>3)*256 ----
    {
        const int rbase = 4 * (w & 7);
        const int half = w >> 3;
        const int J0 = half * 256;
        const int jp = l >> 3, cq = l & 7;
        float acc[4][4];
        #pragma unroll
        for (int rr = 0; rr < 4; rr++)
            #pragma unroll
            for (int k = 0; k < 4; k++) acc[rr][k] = 0.f;

        #pragma unroll 2
        for (int jjc = 0; jjc < 8; jjc++) {
            const int jbase = J0 + jjc * 32 + jp;
            #pragma unroll
            for (int g = 0; g < 8; g++) {
                const int jrow = jbase + g * 4;
                float4 xv = *(const float4*)&xl_s[jrow * XL_ST + cq * 4];
                #pragma unroll
                for (int rr = 0; rr < 4; rr++) {
                    float p = e_s[(rbase + rr) * ES_ST + jrow];
                    acc[rr][0] += p * xv.x;
                    acc[rr][1] += p * xv.y;
                    acc[rr][2] += p * xv.z;
                    acc[rr][3] += p * xv.w;
                }
            }
        }
        // reduce over jp (lane bits 3,4)
        #pragma unroll
        for (int off = 8; off <= 16; off <<= 1)
            #pragma unroll
            for (int rr = 0; rr < 4; rr++)
                #pragma unroll
                for (int k = 0; k < 4; k++)
                    acc[rr][k] += __shfl_xor_sync(0xffffffffu, acc[rr][k], off);

        if (l < 8) {
            #pragma unroll
            for (int rr = 0; rr < 4; rr++)
                *(float4*)&ps_s[half * 1024 + (rbase + rr) * 32 + cq * 4] =
                    make_float4(acc[rr][0], acc[rr][1], acc[rr][2], acc[rr][3]);
        }
    }
    __syncthreads();

    // ---- combine halves + scale + bias + store: warp w rows 2w, 2w+1 ----
    {
        const float bv = bias[h * Cc + l];
        #pragma unroll
        for (int rs = 0; rs < 2; rs++) {
            const int r = 2 * w + rs;
            float val = ps_s[r * 32 + l] + ps_s[1024 + r * 32 + l];
            out[(b * Nn + i0 + r) * ODIM + h * Cc + l] = val * rinv_s[r] + bv;
        }
    }
}

// ---------------------------------------------------------------------------
extern "C" void kernel_launch(void* const* d_in, const int* in_sizes, int n_in,
                              void* d_out, int out_size)
{
    const float* x    = (const float*)d_in[0];
    const int*   adj  = (const int*)  d_in[1];
    const float* Wl   = (const float*)d_in[2];
    const float* bl   = (const float*)d_in[3];
    const float* Wr   = (const float*)d_in[4];
    const float* br   = (const float*)d_in[5];
    const float* att  = (const float*)d_in[6];
    const float* bias = (const float*)d_in[7];
    float* out = (float*)d_out;

    cudaFuncSetAttribute(gat_kernel, cudaFuncAttributeMaxDynamicSharedMemorySize, SMEM_BYTES);

    dim3 g1(Bn * Nn / BM, (2 * ODIM) / BN);   // (64, 4)
    proj_kernel<<<g1, 256>>>(x, Wl, bl, Wr, br);

    dim3 g2(Nn / 32, Hh, Bn);                 // (16, 4, 8)
    gat_kernel<<<g2, 512, SMEM_BYTES>>>(adj, att, bias, out);
}

// round 12
// speedup vs baseline: 1.1479x; 1.1479x over previous
#include <cuda_runtime.h>

// ---------------------------------------------------------------------------
// BatchedGAT: B=8, N=512, IN=256, H=4, C=32, OUT=128, LeakyReLU slope 0.2
// K0: mask precompute: bit-packed adjacency^T + forced diag (int4 + bit-spread)
// K1: projections xl = x@W_l + b_l, xr = x@W_r + b_r  -> [B,H,N,C]
// K2: e_ij = v_j + sum_c 0.4*att_c*|xr_ic + xl_jc|  (linear xr part cancels
//     in softmax; xl part = v_j), masked softmax, out = (p@xl)/rowsum + bias
//     512 threads, 32-row i-tiles, xl in smem; phase D = 8 rows x j-quarter.
// ---------------------------------------------------------------------------

#define Bn 8
#define Nn 512
#define INDIM 256
#define Hh 4
#define Cc 32
#define ODIM 128

typedef unsigned long long u64;

__device__ float g_xl[Bn * Hh * Nn * Cc];        // [b][h][j][c]
__device__ float g_xr[Bn * Hh * Nn * Cc];        // [b][h][i][c]
__device__ unsigned g_mask[Bn * 16 * Nn];        // [b][iw][j], bit i(local 32)

__device__ __forceinline__ u64 f2add(u64 a, u64 b) {
    u64 r; asm("add.rn.f32x2 %0, %1, %2;" : "=l"(r) : "l"(a), "l"(b)); return r;
}
__device__ __forceinline__ u64 f2fma(u64 a, u64 b, u64 c) {
    u64 r; asm("fma.rn.f32x2 %0, %1, %2, %3;" : "=l"(r) : "l"(a), "l"(b), "l"(c)); return r;
}
__device__ __forceinline__ float2 f2unpack(u64 v) {
    float2 r; asm("mov.b64 {%0, %1}, %2;" : "=f"(r.x), "=f"(r.y) : "l"(v)); return r;
}

#define ABSMASK 0x7FFFFFFF7FFFFFFFULL
#define NEGINF  __int_as_float(0xff800000)

// spread bits 0..7 of b to positions 0,4,8,...,28
__device__ __forceinline__ unsigned spread8(unsigned x) {
    x &= 0xFFu;
    x = (x | (x << 12)) & 0x000F000Fu;
    x = (x | (x << 6))  & 0x03030303u;
    x = (x | (x << 3))  & 0x11111111u;
    return x;
}

// ---------------------------------------------------------------------------
// Kernel 0: mask precompute. grid (8, 32), block 256 (8 warps x 2 j-rows).
// Warp reads row j via 4x LDG.128, ballots nibble bits, bit-spreads into
// the 16 transposed mask words. Lanes 0..15 store one word each.
// ---------------------------------------------------------------------------
__global__ void __launch_bounds__(256) mask_kernel(const int* __restrict__ adj)
{
    const int b = blockIdx.x;
    const int w = threadIdx.x >> 5, l = threadIdx.x & 31;
    unsigned* dstb = g_mask + b * 16 * Nn;

    #pragma unroll
    for (int jo = 0; jo < 2; jo++) {
        const int j = blockIdx.y * 16 + w * 2 + jo;
        const int4* arow = (const int4*)(adj + (b * Nn + j) * Nn);

        int4 a4[4];
        #pragma unroll
        for (int q = 0; q < 4; q++) a4[q] = arow[q * 32 + l];   // col q*128+4l

        unsigned bal[4][4];
        #pragma unroll
        for (int q = 0; q < 4; q++) {
            unsigned nib = (unsigned)(a4[q].x != 0)
                         | ((unsigned)(a4[q].y != 0) << 1)
                         | ((unsigned)(a4[q].z != 0) << 2)
                         | ((unsigned)(a4[q].w != 0) << 3);
            const unsigned d = (unsigned)(j - (q * 128 + 4 * l));
            if (d < 4u) nib |= 1u << d;                          // forced diagonal
            #pragma unroll
            for (int k = 0; k < 4; k++)
                bal[q][k] = __ballot_sync(0xffffffffu, (nib >> k) & 1u);
        }

        // lane l<16 builds word for iw=l: q=l>>2, byte s=l&3
        if (l < 16) {
            const int q = l >> 2, s = l & 3;
            unsigned word = 0;
            #pragma unroll
            for (int k = 0; k < 4; k++)
                word |= spread8(bal[q][k] >> (8 * s)) << k;
            dstb[l * Nn + j] = word;
        }
    }
}

// ---------------------------------------------------------------------------
// Kernel 1: tiled SIMT GEMM. M=4096, K=256, Ncols=256 (xl | xr)
// ---------------------------------------------------------------------------
#define BM 64
#define BN 64
#define BK 16

__global__ void __launch_bounds__(256) proj_kernel(
    const float* __restrict__ x,
    const float* __restrict__ Wl, const float* __restrict__ bl,
    const float* __restrict__ Wr, const float* __restrict__ br)
{
    __shared__ float As[BK][BM + 4];
    __shared__ float Bs[BK][BN + 4];

    const int tid = threadIdx.x;
    const int m0 = blockIdx.x * BM;
    const int n0 = blockIdx.y * BN;
    const float* W  = (n0 < 128) ? Wl : Wr;
    const float* bb = (n0 < 128) ? bl : br;
    float* dstg     = (n0 < 128) ? g_xl : g_xr;
    const int wcol0 = n0 & 127;

    const int ty = tid >> 4;
    const int tx = tid & 15;
    const int ar  = tid >> 2;
    const int ak4 = (tid & 3) << 2;
    const int bk  = tid >> 4;
    const int bn4 = (tid & 15) << 2;

    float acc[4][4];
    #pragma unroll
    for (int r = 0; r < 4; r++)
        #pragma unroll
        for (int c = 0; c < 4; c++) acc[r][c] = 0.f;

    for (int k0 = 0; k0 < INDIM; k0 += BK) {
        float4 av = *(const float4*)&x[(m0 + ar) * INDIM + k0 + ak4];
        As[ak4 + 0][ar] = av.x;
        As[ak4 + 1][ar] = av.y;
        As[ak4 + 2][ar] = av.z;
        As[ak4 + 3][ar] = av.w;
        float4 bv = *(const float4*)&W[(k0 + bk) * ODIM + wcol0 + bn4];
        *(float4*)&Bs[bk][bn4] = bv;
        __syncthreads();

        #pragma unroll
        for (int kk = 0; kk < BK; kk++) {
            float4 a = *(const float4*)&As[kk][ty * 4];
            float4 b = *(const float4*)&Bs[kk][tx * 4];
            float aa[4] = {a.x, a.y, a.z, a.w};
            float bbv[4] = {b.x, b.y, b.z, b.w};
            #pragma unroll
            for (int r = 0; r < 4; r++)
                #pragma unroll
                for (int c = 0; c < 4; c++) acc[r][c] += aa[r] * bbv[c];
        }
        __syncthreads();
    }

    const int oc0 = n0 + tx * 4;
    const int h   = (oc0 & 127) >> 5;
    const int ch  = oc0 & 31;
    float4 bias4;
    bias4.x = bb[wcol0 + tx * 4 + 0];
    bias4.y = bb[wcol0 + tx * 4 + 1];
    bias4.z = bb[wcol0 + tx * 4 + 2];
    bias4.w = bb[wcol0 + tx * 4 + 3];

    #pragma unroll
    for (int r = 0; r < 4; r++) {
        const int m = m0 + ty * 4 + r;
        const int bidx = m >> 9;
        const int n = m & 511;
        float4 v;
        v.x = acc[r][0] + bias4.x;
        v.y = acc[r][1] + bias4.y;
        v.z = acc[r][2] + bias4.z;
        v.w = acc[r][3] + bias4.w;
        *(float4*)&dstg[(((bidx * Hh + h) * Nn) + n) * Cc + ch] = v;
    }
}

// ---------------------------------------------------------------------------
// Kernel 2: attention. grid (16, 4, 8), 512 threads.
// ---------------------------------------------------------------------------
#define XL_ST 36
#define ES_ST 516
#define SM_XL   0                          // 512*36 = 18432
#define SM_XR   (SM_XL + Nn * XL_ST)       // 1024
#define SM_ES   (SM_XR + 1024)             // 32*516 = 16512
#define SM_MASK (SM_ES + 32 * ES_ST)       // 512
#define SM_W4   (SM_MASK + 512)            // 32
#define SM_W6   (SM_W4 + 32)               // 32
#define SM_RINV (SM_W6 + 32)               // 32
#define SM_PS   (SM_RINV + 32)             // 4 quarters * 32 rows * 32 ch = 4096
#define SM_FLOATS (SM_PS + 4096)
#define SMEM_BYTES (SM_FLOATS * 4)         // 162688 bytes

__global__ void __launch_bounds__(512) gat_kernel(
    const float* __restrict__ att,
    const float* __restrict__ bias,
    float* __restrict__ out)
{
    extern __shared__ float sm[];
    float* xl_s = sm + SM_XL;
    float* xr_s = sm + SM_XR;
    float* e_s  = sm + SM_ES;
    unsigned* mask_s = (unsigned*)(sm + SM_MASK);
    float* w4_s = sm + SM_W4;
    float* w6_s = sm + SM_W6;
    float* rinv_s = sm + SM_RINV;
    float* ps_s = sm + SM_PS;

    const int tid = threadIdx.x;
    const int w = tid >> 5;
    const int l = tid & 31;
    const int b  = blockIdx.z;
    const int h  = blockIdx.y;
    const int bx = blockIdx.x;
    const int i0 = bx * 32;

    const float* xl = g_xl + ((b * Hh + h) * Nn) * Cc;
    const float* xr = g_xr + ((b * Hh + h) * Nn + i0) * Cc;

    // ---- loads ----
    mask_s[tid] = g_mask[(b * 16 + bx) * Nn + tid];
    if (tid < 32) {
        float a = att[h * Cc + tid];
        w4_s[tid] = 0.4f * a;
        w6_s[tid] = 0.6f * a;
    }
    #pragma unroll
    for (int q8 = 0; q8 < 8; q8++) {
        int idx = q8 * 512 + tid;          // 4096 float4
        int j = idx >> 3, cc = (idx & 7) << 2;
        *(float4*)&xl_s[j * XL_ST + cc] = *(const float4*)&xl[j * Cc + cc];
    }
    if (tid < 256) {
        int j = tid >> 3, cc = (tid & 7) << 2;
        *(float4*)&xr_s[j * Cc + cc] = *(const float4*)&xr[j * Cc + cc];
    }
    __syncthreads();

    // ---- Phase 1: e scores, j-sliced. Warp w owns j = 32w + l ----
    {
        const int j = tid;
        u64 q[16];
        {
            const ulonglong2* qp = (const ulonglong2*)&xl_s[j * XL_ST];
            #pragma unroll
            for (int k = 0; k < 8; k++) { ulonglong2 t = qp[k]; q[2*k] = t.x; q[2*k+1] = t.y; }
        }
        u64 w4r[16];
        {
            const ulonglong2* wp = (const ulonglong2*)w4_s;
            #pragma unroll
            for (int k = 0; k < 8; k++) { ulonglong2 t = wp[k]; w4r[2*k] = t.x; w4r[2*k+1] = t.y; }
        }
        float v;
        {
            const u64* w6p = (const u64*)w6_s;
            u64 va = 0ull, vb = 0ull;
            #pragma unroll
            for (int k = 0; k < 16; k += 2) {
                va = f2fma(w6p[k],   q[k],   va);
                vb = f2fma(w6p[k+1], q[k+1], vb);
            }
            float2 f = f2unpack(f2add(va, vb));
            v = f.x + f.y;
        }
        const unsigned m = mask_s[j];
        float* erow = &e_s[j];

        #pragma unroll 4
        for (int i = 0; i < 32; i++) {
            const ulonglong2* xp = (const ulonglong2*)&xr_s[i * Cc];
            u64 a0 = 0ull, a1 = 0ull, a2 = 0ull, a3 = 0ull;
            #pragma unroll
            for (int k = 0; k < 8; k += 2) {
                ulonglong2 t0 = xp[k], t1 = xp[k+1];
                u64 s0 = f2add(t0.x, q[2*k])   & ABSMASK;
                u64 s1 = f2add(t0.y, q[2*k+1]) & ABSMASK;
                u64 s2 = f2add(t1.x, q[2*k+2]) & ABSMASK;
                u64 s3 = f2add(t1.y, q[2*k+3]) & ABSMASK;
                a0 = f2fma(w4r[2*k],   s0, a0);
                a1 = f2fma(w4r[2*k+1], s1, a1);
                a2 = f2fma(w4r[2*k+2], s2, a2);
                a3 = f2fma(w4r[2*k+3], s3, a3);
            }
            float2 f = f2unpack(f2add(f2add(a0, a1), f2add(a2, a3)));
            float e = f.x + f.y + v;
            e = ((m >> i) & 1u) ? e : NEGINF;
            erow[i * ES_ST] = e;
        }
    }
    __syncthreads();

    // ---- Phase 2: masked softmax. Warp w owns rows 2w, 2w+1 ----
    #pragma unroll
    for (int rs = 0; rs < 2; rs++) {
        const int r = 2 * w + rs;
        float vals[16];
        #pragma unroll
        for (int p4 = 0; p4 < 4; p4++) {
            float4 f = *(float4*)&e_s[r * ES_ST + p4 * 128 + l * 4];
            vals[p4*4]   = f.x; vals[p4*4+1] = f.y;
            vals[p4*4+2] = f.z; vals[p4*4+3] = f.w;
        }
        float mx = vals[0];
        #pragma unroll
        for (int k = 1; k < 16; k++) mx = fmaxf(mx, vals[k]);
        #pragma unroll
        for (int off = 16; off > 0; off >>= 1)
            mx = fmaxf(mx, __shfl_xor_sync(0xffffffffu, mx, off));
        float sum = 0.f;
        #pragma unroll
        for (int k = 0; k < 16; k++) {
            float p = __expf(vals[k] - mx);
            vals[k] = p;
            sum += p;
        }
        #pragma unroll
        for (int off = 16; off > 0; off >>= 1)
            sum += __shfl_xor_sync(0xffffffffu, sum, off);
        #pragma unroll
        for (int p4 = 0; p4 < 4; p4++) {
            *(float4*)&e_s[r * ES_ST + p4 * 128 + l * 4] =
                make_float4(vals[p4*4], vals[p4*4+1], vals[p4*4+2], vals[p4*4+3]);
        }
        if (l == 0) rinv_s[r] = 1.f / sum;
    }
    __syncthreads();

    // ---- Phase D: warp w -> rows 8*(w&3)..+7, j-quarter (w>>2)*128 ----
    {
        const int rbase = 8 * (w & 3);
        const int q4 = w >> 2;
        const int J0 = q4 * 128;
        const int jp = l >> 3, cq = l & 7;
        float acc[8][4];
        #pragma unroll
        for (int rr = 0; rr < 8; rr++)
            #pragma unroll
            for (int k = 0; k < 4; k++) acc[rr][k] = 0.f;

        #pragma unroll 4
        for (int it = 0; it < 32; it++) {
            const int jrow = J0 + it * 4 + jp;
            float4 xv = *(const float4*)&xl_s[jrow * XL_ST + cq * 4];
            #pragma unroll
            for (int rr = 0; rr < 8; rr++) {
                float p = e_s[(rbase + rr) * ES_ST + jrow];
                acc[rr][0] += p * xv.x;
                acc[rr][1] += p * xv.y;
                acc[rr][2] += p * xv.z;
                acc[rr][3] += p * xv.w;
            }
        }
        // reduce over jp (lane bits 3,4)
        #pragma unroll
        for (int off = 8; off <= 16; off <<= 1)
            #pragma unroll
            for (int rr = 0; rr < 8; rr++)
                #pragma unroll
                for (int k = 0; k < 4; k++)
                    acc[rr][k] += __shfl_xor_sync(0xffffffffu, acc[rr][k], off);

        if (l < 8) {
            #pragma unroll
            for (int rr = 0; rr < 8; rr++)
                *(float4*)&ps_s[(q4 * 32 + rbase + rr) * 32 + cq * 4] =
                    make_float4(acc[rr][0], acc[rr][1], acc[rr][2], acc[rr][3]);
        }
    }
    __syncthreads();

    // ---- combine quarters + scale + bias + store: warp w rows 2w, 2w+1 ----
    {
        const float bv = bias[h * Cc + l];
        #pragma unroll
        for (int rs = 0; rs < 2; rs++) {
            const int r = 2 * w + rs;
            float val = ps_s[r * 32 + l] + ps_s[(32 + r) * 32 + l]
                      + ps_s[(64 + r) * 32 + l] + ps_s[(96 + r) * 32 + l];
            out[(b * Nn + i0 + r) * ODIM + h * Cc + l] = val * rinv_s[r] + bv;
        }
    }
}

// ---------------------------------------------------------------------------
extern "C" void kernel_launch(void* const* d_in, const int* in_sizes, int n_in,
                              void* d_out, int out_size)
{
    const float* x    = (const float*)d_in[0];
    const int*   adj  = (const int*)  d_in[1];
    const float* Wl   = (const float*)d_in[2];
    const float* bl   = (const float*)d_in[3];
    const float* Wr   = (const float*)d_in[4];
    const float* br   = (const float*)d_in[5];
    const float* att  = (const float*)d_in[6];
    const float* bias = (const float*)d_in[7];
    float* out = (float*)d_out;

    cudaFuncSetAttribute(gat_kernel, cudaFuncAttributeMaxDynamicSharedMemorySize, SMEM_BYTES);

    dim3 g0(Bn, 32);
    mask_kernel<<<g0, 256>>>(adj);

    dim3 g1(Bn * Nn / BM, (2 * ODIM) / BN);   // (64, 4)
    proj_kernel<<<g1, 256>>>(x, Wl, bl, Wr, br);

    dim3 g2(Nn / 32, Hh, Bn);                 // (16, 4, 8)
    gat_kernel<<<g2, 512, SMEM_BYTES>>>(att, bias, out);
}

// round 13
// speedup vs baseline: 1.1648x; 1.0147x over previous
#include <cuda_runtime.h>

// ---------------------------------------------------------------------------
// BatchedGAT: B=8, N=512, IN=256, H=4, C=32, OUT=128, LeakyReLU slope 0.2
// K0: mask precompute: bit-packed adjacency^T + forced diag
// K1: projections xl = x@W_l + b_l, xr = x@W_r + b_r  -> [B,H,N,C]
// K2: e_ij = v_j + sum_c 0.4*att_c*|xr_ic + xl_jc|  (linear xr part cancels
//     in softmax; xl part = v_j), masked softmax (no max-sub; e bounded),
//     out = (p@xl)/rowsum + bias. Scores kept TRANSPOSED: es_t[j][i].
//     512 threads, 32-row i-tiles, xl in smem; phase D = 8 rows x j-quarter.
// ---------------------------------------------------------------------------

#define Bn 8
#define Nn 512
#define INDIM 256
#define Hh 4
#define Cc 32
#define ODIM 128

typedef unsigned long long u64;

__device__ float g_xl[Bn * Hh * Nn * Cc];        // [b][h][j][c]
__device__ float g_xr[Bn * Hh * Nn * Cc];        // [b][h][i][c]
__device__ unsigned g_mask[Bn * 16 * Nn];        // [b][iw][j], bit i(local 32)

__device__ __forceinline__ u64 f2add(u64 a, u64 b) {
    u64 r; asm("add.rn.f32x2 %0, %1, %2;" : "=l"(r) : "l"(a), "l"(b)); return r;
}
__device__ __forceinline__ u64 f2fma(u64 a, u64 b, u64 c) {
    u64 r; asm("fma.rn.f32x2 %0, %1, %2, %3;" : "=l"(r) : "l"(a), "l"(b), "l"(c)); return r;
}
__device__ __forceinline__ float2 f2unpack(u64 v) {
    float2 r; asm("mov.b64 {%0, %1}, %2;" : "=f"(r.x), "=f"(r.y) : "l"(v)); return r;
}

#define ABSMASK 0x7FFFFFFF7FFFFFFFULL
#define NEGINF  __int_as_float(0xff800000)

// ---------------------------------------------------------------------------
// Kernel 0: mask precompute. grid (8, 16, 4), block 256; warp owns 16 j's.
// ---------------------------------------------------------------------------
__global__ void __launch_bounds__(256) mask_kernel(const int* __restrict__ adj)
{
    const int b = blockIdx.x, iw = blockIdx.y, jc = blockIdx.z;
    const int w = threadIdx.x >> 5, l = threadIdx.x & 31;
    const int ig = iw * 32 + l;
    const int* a = adj + b * Nn * Nn + iw * 32 + l;
    unsigned* dst = g_mask + (b * 16 + iw) * Nn;
    const int j0 = jc * 128 + w * 16;

    int av[16];
    #pragma unroll
    for (int k = 0; k < 16; k++) av[k] = a[(j0 + k) * Nn];   // MLP 16
    #pragma unroll
    for (int k = 0; k < 16; k++) {
        const int j = j0 + k;
        unsigned word = __ballot_sync(0xffffffffu, (av[k] != 0) || (j == ig));
        if (l == 0) dst[j] = word;
    }
}

// ---------------------------------------------------------------------------
// Kernel 1: tiled SIMT GEMM. M=4096, K=256, Ncols=256 (xl | xr)
// ---------------------------------------------------------------------------
#define BM 64
#define BN 64
#define BK 16

__global__ void __launch_bounds__(256) proj_kernel(
    const float* __restrict__ x,
    const float* __restrict__ Wl, const float* __restrict__ bl,
    const float* __restrict__ Wr, const float* __restrict__ br)
{
    __shared__ float As[BK][BM + 4];
    __shared__ float Bs[BK][BN + 4];

    const int tid = threadIdx.x;
    const int m0 = blockIdx.x * BM;
    const int n0 = blockIdx.y * BN;
    const float* W  = (n0 < 128) ? Wl : Wr;
    const float* bb = (n0 < 128) ? bl : br;
    float* dstg     = (n0 < 128) ? g_xl : g_xr;
    const int wcol0 = n0 & 127;

    const int ty = tid >> 4;
    const int tx = tid & 15;
    const int ar  = tid >> 2;
    const int ak4 = (tid & 3) << 2;
    const int bk  = tid >> 4;
    const int bn4 = (tid & 15) << 2;

    float acc[4][4];
    #pragma unroll
    for (int r = 0; r < 4; r++)
        #pragma unroll
        for (int c = 0; c < 4; c++) acc[r][c] = 0.f;

    for (int k0 = 0; k0 < INDIM; k0 += BK) {
        float4 av = *(const float4*)&x[(m0 + ar) * INDIM + k0 + ak4];
        As[ak4 + 0][ar] = av.x;
        As[ak4 + 1][ar] = av.y;
        As[ak4 + 2][ar] = av.z;
        As[ak4 + 3][ar] = av.w;
        float4 bv = *(const float4*)&W[(k0 + bk) * ODIM + wcol0 + bn4];
        *(float4*)&Bs[bk][bn4] = bv;
        __syncthreads();

        #pragma unroll
        for (int kk = 0; kk < BK; kk++) {
            float4 a = *(const float4*)&As[kk][ty * 4];
            float4 b = *(const float4*)&Bs[kk][tx * 4];
            float aa[4] = {a.x, a.y, a.z, a.w};
            float bbv[4] = {b.x, b.y, b.z, b.w};
            #pragma unroll
            for (int r = 0; r < 4; r++)
                #pragma unroll
                for (int c = 0; c < 4; c++) acc[r][c] += aa[r] * bbv[c];
        }
        __syncthreads();
    }

    const int oc0 = n0 + tx * 4;
    const int h   = (oc0 & 127) >> 5;
    const int ch  = oc0 & 31;
    float4 bias4;
    bias4.x = bb[wcol0 + tx * 4 + 0];
    bias4.y = bb[wcol0 + tx * 4 + 1];
    bias4.z = bb[wcol0 + tx * 4 + 2];
    bias4.w = bb[wcol0 + tx * 4 + 3];

    #pragma unroll
    for (int r = 0; r < 4; r++) {
        const int m = m0 + ty * 4 + r;
        const int bidx = m >> 9;
        const int n = m & 511;
        float4 v;
        v.x = acc[r][0] + bias4.x;
        v.y = acc[r][1] + bias4.y;
        v.z = acc[r][2] + bias4.z;
        v.w = acc[r][3] + bias4.w;
        *(float4*)&dstg[(((bidx * Hh + h) * Nn) + n) * Cc + ch] = v;
    }
}

// ---------------------------------------------------------------------------
// Kernel 2: attention. grid (16, 4, 8), 512 threads. Transposed score buf.
// ---------------------------------------------------------------------------
#define XL_ST 36
#define ET_ST 36                           // es_t[j][i], stride 36
#define SM_XL   0                          // 512*36 = 18432
#define SM_XR   (SM_XL + Nn * XL_ST)       // 1024
#define SM_ET   (SM_XR + 1024)             // 512*36 = 18432
#define SM_MASK (SM_ET + Nn * ET_ST)       // 512
#define SM_W4   (SM_MASK + 512)            // 32
#define SM_W6   (SM_W4 + 32)               // 32
#define SM_RINV (SM_W6 + 32)               // 32
#define SM_PS   (SM_RINV + 32)             // 4 quarters * 32 rows * 32 ch = 4096
#define SM_FLOATS (SM_PS + 4096)
#define SMEM_BYTES (SM_FLOATS * 4)         // 170368 bytes

__global__ void __launch_bounds__(512) gat_kernel(
    const float* __restrict__ att,
    const float* __restrict__ bias,
    float* __restrict__ out)
{
    extern __shared__ float sm[];
    float* xl_s = sm + SM_XL;
    float* xr_s = sm + SM_XR;
    float* et_s = sm + SM_ET;
    unsigned* mask_s = (unsigned*)(sm + SM_MASK);
    float* w4_s = sm + SM_W4;
    float* w6_s = sm + SM_W6;
    float* rinv_s = sm + SM_RINV;
    float* ps_s = sm + SM_PS;

    const int tid = threadIdx.x;
    const int w = tid >> 5;
    const int l = tid & 31;
    const int b  = blockIdx.z;
    const int h  = blockIdx.y;
    const int bx = blockIdx.x;
    const int i0 = bx * 32;

    const float* xl = g_xl + ((b * Hh + h) * Nn) * Cc;
    const float* xr = g_xr + ((b * Hh + h) * Nn + i0) * Cc;

    // ---- loads ----
    mask_s[tid] = g_mask[(b * 16 + bx) * Nn + tid];
    if (tid < 32) {
        float a = att[h * Cc + tid];
        w4_s[tid] = 0.4f * a;
        w6_s[tid] = 0.6f * a;
    }
    #pragma unroll
    for (int q8 = 0; q8 < 8; q8++) {
        int idx = q8 * 512 + tid;          // 4096 float4
        int j = idx >> 3, cc = (idx & 7) << 2;
        *(float4*)&xl_s[j * XL_ST + cc] = *(const float4*)&xl[j * Cc + cc];
    }
    if (tid < 256) {
        int j = tid >> 3, cc = (tid & 7) << 2;
        *(float4*)&xr_s[j * Cc + cc] = *(const float4*)&xr[j * Cc + cc];
    }
    __syncthreads();

    // ---- Phase 1: e scores, j-sliced. Thread owns j = tid; stores es_t[j][i]
    {
        const int j = tid;
        u64 q[16];
        {
            const ulonglong2* qp = (const ulonglong2*)&xl_s[j * XL_ST];
            #pragma unroll
            for (int k = 0; k < 8; k++) { ulonglong2 t = qp[k]; q[2*k] = t.x; q[2*k+1] = t.y; }
        }
        u64 w4r[16];
        {
            const ulonglong2* wp = (const ulonglong2*)w4_s;
            #pragma unroll
            for (int k = 0; k < 8; k++) { ulonglong2 t = wp[k]; w4r[2*k] = t.x; w4r[2*k+1] = t.y; }
        }
        float v;
        {
            const u64* w6p = (const u64*)w6_s;
            u64 va = 0ull, vb = 0ull;
            #pragma unroll
            for (int k = 0; k < 16; k += 2) {
                va = f2fma(w6p[k],   q[k],   va);
                vb = f2fma(w6p[k+1], q[k+1], vb);
            }
            float2 f = f2unpack(f2add(va, vb));
            v = f.x + f.y;
        }
        const unsigned m = mask_s[j];
        float* erow = &et_s[j * ET_ST];

        #pragma unroll 2
        for (int ig = 0; ig < 8; ig++) {
            float ev[4];
            #pragma unroll
            for (int ii = 0; ii < 4; ii++) {
                const int i = ig * 4 + ii;
                const ulonglong2* xp = (const ulonglong2*)&xr_s[i * Cc];
                u64 a0 = 0ull, a1 = 0ull, a2 = 0ull, a3 = 0ull;
                #pragma unroll
                for (int k = 0; k < 8; k += 2) {
                    ulonglong2 t0 = xp[k], t1 = xp[k+1];
                    u64 s0 = f2add(t0.x, q[2*k])   & ABSMASK;
                    u64 s1 = f2add(t0.y, q[2*k+1]) & ABSMASK;
                    u64 s2 = f2add(t1.x, q[2*k+2]) & ABSMASK;
                    u64 s3 = f2add(t1.y, q[2*k+3]) & ABSMASK;
                    a0 = f2fma(w4r[2*k],   s0, a0);
                    a1 = f2fma(w4r[2*k+1], s1, a1);
                    a2 = f2fma(w4r[2*k+2], s2, a2);
                    a3 = f2fma(w4r[2*k+3], s3, a3);
                }
                float2 f = f2unpack(f2add(f2add(a0, a1), f2add(a2, a3)));
                float e = f.x + f.y + v;
                ev[ii] = ((m >> i) & 1u) ? e : NEGINF;
            }
            *(float4*)&erow[ig * 4] = make_float4(ev[0], ev[1], ev[2], ev[3]);
        }
    }
    __syncthreads();

    // ---- Phase 2: softmax over j (no max-sub; e bounded, exp(-inf)=0) ----
    // Warp w owns rows 2w, 2w+1.
    #pragma unroll
    for (int rs = 0; rs < 2; rs++) {
        const int r = 2 * w + rs;
        float sum = 0.f;
        #pragma unroll
        for (int k = 0; k < 16; k++) {
            const int j = k * 32 + l;
            float p = __expf(et_s[j * ET_ST + r]);
            et_s[j * ET_ST + r] = p;
            sum += p;
        }
        #pragma unroll
        for (int off = 16; off > 0; off >>= 1)
            sum += __shfl_xor_sync(0xffffffffu, sum, off);
        if (l == 0) rinv_s[r] = 1.f / sum;
    }
    __syncthreads();

    // ---- Phase D: warp w -> rows 8*(w&3)..+7, j-quarter (w>>2)*128 ----
    {
        const int rbase = 8 * (w & 3);
        const int q4 = w >> 2;
        const int J0 = q4 * 128;
        const int jp = l >> 3, cq = l & 7;
        float acc[8][4];
        #pragma unroll
        for (int rr = 0; rr < 8; rr++)
            #pragma unroll
            for (int k = 0; k < 4; k++) acc[rr][k] = 0.f;

        #pragma unroll 4
        for (int it = 0; it < 32; it++) {
            const int jrow = J0 + it * 4 + jp;
            float4 xv = *(const float4*)&xl_s[jrow * XL_ST + cq * 4];
            float4 p0 = *(const float4*)&et_s[jrow * ET_ST + rbase];
            float4 p1 = *(const float4*)&et_s[jrow * ET_ST + rbase + 4];
            acc[0][0] += p0.x * xv.x; acc[0][1] += p0.x * xv.y;
            acc[0][2] += p0.x * xv.z; acc[0][3] += p0.x * xv.w;
            acc[1][0] += p0.y * xv.x; acc[1][1] += p0.y * xv.y;
            acc[1][2] += p0.y * xv.z; acc[1][3] += p0.y * xv.w;
            acc[2][0] += p0.z * xv.x; acc[2][1] += p0.z * xv.y;
            acc[2][2] += p0.z * xv.z; acc[2][3] += p0.z * xv.w;
            acc[3][0] += p0.w * xv.x; acc[3][1] += p0.w * xv.y;
            acc[3][2] += p0.w * xv.z; acc[3][3] += p0.w * xv.w;
            acc[4][0] += p1.x * xv.x; acc[4][1] += p1.x * xv.y;
            acc[4][2] += p1.x * xv.z; acc[4][3] += p1.x * xv.w;
            acc[5][0] += p1.y * xv.x; acc[5][1] += p1.y * xv.y;
            acc[5][2] += p1.y * xv.z; acc[5][3] += p1.y * xv.w;
            acc[6][0] += p1.z * xv.x; acc[6][1] += p1.z * xv.y;
            acc[6][2] += p1.z * xv.z; acc[6][3] += p1.z * xv.w;
            acc[7][0] += p1.w * xv.x; acc[7][1] += p1.w * xv.y;
            acc[7][2] += p1.w * xv.z; acc[7][3] += p1.w * xv.w;
        }
        // reduce over jp (lane bits 3,4)
        #pragma unroll
        for (int off = 8; off <= 16; off <<= 1)
            #pragma unroll
            for (int rr = 0; rr < 8; rr++)
                #pragma unroll
                for (int k = 0; k < 4; k++)
                    acc[rr][k] += __shfl_xor_sync(0xffffffffu, acc[rr][k], off);

        if (l < 8) {
            #pragma unroll
            for (int rr = 0; rr < 8; rr++)
                *(float4*)&ps_s[(q4 * 32 + rbase + rr) * 32 + cq * 4] =
                    make_float4(acc[rr][0], acc[rr][1], acc[rr][2], acc[rr][3]);
        }
    }
    __syncthreads();

    // ---- combine quarters + scale + bias + store: warp w rows 2w, 2w+1 ----
    {
        const float bv = bias[h * Cc + l];
        #pragma unroll
        for (int rs = 0; rs < 2; rs++) {
            const int r = 2 * w + rs;
            float val = ps_s[r * 32 + l] + ps_s[(32 + r) * 32 + l]
                      + ps_s[(64 + r) * 32 + l] + ps_s[(96 + r) * 32 + l];
            out[(b * Nn + i0 + r) * ODIM + h * Cc + l] = val * rinv_s[r] + bv;
        }
    }
}

// ---------------------------------------------------------------------------
extern "C" void kernel_launch(void* const* d_in, const int* in_sizes, int n_in,
                              void* d_out, int out_size)
{
    const float* x    = (const float*)d_in[0];
    const int*   adj  = (const int*)  d_in[1];
    const float* Wl   = (const float*)d_in[2];
    const float* bl   = (const float*)d_in[3];
    const float* Wr   = (const float*)d_in[4];
    const float* br   = (const float*)d_in[5];
    const float* att  = (const float*)d_in[6];
    const float* bias = (const float*)d_in[7];
    float* out = (float*)d_out;

    cudaFuncSetAttribute(gat_kernel, cudaFuncAttributeMaxDynamicSharedMemorySize, SMEM_BYTES);

    dim3 g0(Bn, 16, 4);
    mask_kernel<<<g0, 256>>>(adj);

    dim3 g1(Bn * Nn / BM, (2 * ODIM) / BN);   // (64, 4)
    proj_kernel<<<g1, 256>>>(x, Wl, bl, Wr, br);

    dim3 g2(Nn / 32, Hh, Bn);                 // (16, 4, 8)
    gat_kernel<<<g2, 512, SMEM_BYTES>>>(att, bias, out);
}

// round 14
// speedup vs baseline: 1.2225x; 1.0495x over previous
#include <cuda_runtime.h>

// ---------------------------------------------------------------------------
// BatchedGAT: B=8, N=512, IN=256, H=4, C=32, OUT=128, LeakyReLU slope 0.2
// K1: projections xl = x@W_l + b_l, xr = x@W_r + b_r  -> [B,H,N,C]
// K2: p_ij = mask ? exp(v_j + sum_c 0.4*att_c*|xr_ic + xl_jc|) : 0
//     (linear xr part cancels in softmax; xl part = v_j; no max-sub needed,
//     e is bounded). Mask built in-register via coalesced row ballots.
//     out = (p @ xl) / rowsum + bias. Scores TRANSPOSED: et_s[j][i].
//     512 threads, 32-row i-tiles; phase D = 8 rows x j-quarter.
// ---------------------------------------------------------------------------

#define Bn 8
#define Nn 512
#define INDIM 256
#define Hh 4
#define Cc 32
#define ODIM 128

typedef unsigned long long u64;

__device__ float g_xl[Bn * Hh * Nn * Cc];        // [b][h][j][c]
__device__ float g_xr[Bn * Hh * Nn * Cc];        // [b][h][i][c]

__device__ __forceinline__ u64 f2add(u64 a, u64 b) {
    u64 r; asm("add.rn.f32x2 %0, %1, %2;" : "=l"(r) : "l"(a), "l"(b)); return r;
}
__device__ __forceinline__ u64 f2fma(u64 a, u64 b, u64 c) {
    u64 r; asm("fma.rn.f32x2 %0, %1, %2, %3;" : "=l"(r) : "l"(a), "l"(b), "l"(c)); return r;
}
__device__ __forceinline__ float2 f2unpack(u64 v) {
    float2 r; asm("mov.b64 {%0, %1}, %2;" : "=f"(r.x), "=f"(r.y) : "l"(v)); return r;
}

#define ABSMASK 0x7FFFFFFF7FFFFFFFULL

// ---------------------------------------------------------------------------
// Kernel 1: tiled SIMT GEMM. M=4096, K=256, Ncols=256 (xl | xr)
// ---------------------------------------------------------------------------
#define BM 64
#define BN 64
#define BK 16

__global__ void __launch_bounds__(256) proj_kernel(
    const float* __restrict__ x,
    const float* __restrict__ Wl, const float* __restrict__ bl,
    const float* __restrict__ Wr, const float* __restrict__ br)
{
    __shared__ float As[BK][BM + 4];
    __shared__ float Bs[BK][BN + 4];

    const int tid = threadIdx.x;
    const int m0 = blockIdx.x * BM;
    const int n0 = blockIdx.y * BN;
    const float* W  = (n0 < 128) ? Wl : Wr;
    const float* bb = (n0 < 128) ? bl : br;
    float* dstg     = (n0 < 128) ? g_xl : g_xr;
    const int wcol0 = n0 & 127;

    const int ty = tid >> 4;
    const int tx = tid & 15;
    const int ar  = tid >> 2;
    const int ak4 = (tid & 3) << 2;
    const int bk  = tid >> 4;
    const int bn4 = (tid & 15) << 2;

    float acc[4][4];
    #pragma unroll
    for (int r = 0; r < 4; r++)
        #pragma unroll
        for (int c = 0; c < 4; c++) acc[r][c] = 0.f;

    for (int k0 = 0; k0 < INDIM; k0 += BK) {
        float4 av = *(const float4*)&x[(m0 + ar) * INDIM + k0 + ak4];
        As[ak4 + 0][ar] = av.x;
        As[ak4 + 1][ar] = av.y;
        As[ak4 + 2][ar] = av.z;
        As[ak4 + 3][ar] = av.w;
        float4 bv = *(const float4*)&W[(k0 + bk) * ODIM + wcol0 + bn4];
        *(float4*)&Bs[bk][bn4] = bv;
        __syncthreads();

        #pragma unroll
        for (int kk = 0; kk < BK; kk++) {
            float4 a = *(const float4*)&As[kk][ty * 4];
            float4 b = *(const float4*)&Bs[kk][tx * 4];
            float aa[4] = {a.x, a.y, a.z, a.w};
            float bbv[4] = {b.x, b.y, b.z, b.w};
            #pragma unroll
            for (int r = 0; r < 4; r++)
                #pragma unroll
                for (int c = 0; c < 4; c++) acc[r][c] += aa[r] * bbv[c];
        }
        __syncthreads();
    }

    const int oc0 = n0 + tx * 4;
    const int h   = (oc0 & 127) >> 5;
    const int ch  = oc0 & 31;
    float4 bias4;
    bias4.x = bb[wcol0 + tx * 4 + 0];
    bias4.y = bb[wcol0 + tx * 4 + 1];
    bias4.z = bb[wcol0 + tx * 4 + 2];
    bias4.w = bb[wcol0 + tx * 4 + 3];

    #pragma unroll
    for (int r = 0; r < 4; r++) {
        const int m = m0 + ty * 4 + r;
        const int bidx = m >> 9;
        const int n = m & 511;
        float4 v;
        v.x = acc[r][0] + bias4.x;
        v.y = acc[r][1] + bias4.y;
        v.z = acc[r][2] + bias4.z;
        v.w = acc[r][3] + bias4.w;
        *(float4*)&dstg[(((bidx * Hh + h) * Nn) + n) * Cc + ch] = v;
    }
}

// ---------------------------------------------------------------------------
// Kernel 2: attention. grid (16, 4, 8), 512 threads. Transposed score buf,
// in-register ballot mask, exp fused into phase 1.
// ---------------------------------------------------------------------------
#define XL_ST 36
#define ET_ST 36                           // et_s[j][i], stride 36
#define SM_XL   0                          // 512*36 = 18432
#define SM_XR   (SM_XL + Nn * XL_ST)       // 1024
#define SM_ET   (SM_XR + 1024)             // 512*36 = 18432
#define SM_W4   (SM_ET + Nn * ET_ST)       // 32
#define SM_W6   (SM_W4 + 32)               // 32
#define SM_RINV (SM_W6 + 32)               // 32
#define SM_PS   (SM_RINV + 32)             // 4 quarters * 32 rows * 32 ch = 4096
#define SM_FLOATS (SM_PS + 4096)
#define SMEM_BYTES (SM_FLOATS * 4)         // 168320 bytes

__global__ void __launch_bounds__(512) gat_kernel(
    const int* __restrict__ adj,
    const float* __restrict__ att,
    const float* __restrict__ bias,
    float* __restrict__ out)
{
    extern __shared__ float sm[];
    float* xl_s = sm + SM_XL;
    float* xr_s = sm + SM_XR;
    float* et_s = sm + SM_ET;
    float* w4_s = sm + SM_W4;
    float* w6_s = sm + SM_W6;
    float* rinv_s = sm + SM_RINV;
    float* ps_s = sm + SM_PS;

    const int tid = threadIdx.x;
    const int w = tid >> 5;
    const int l = tid & 31;
    const int b  = blockIdx.z;
    const int h  = blockIdx.y;
    const int bx = blockIdx.x;
    const int i0 = bx * 32;

    const float* xl = g_xl + ((b * Hh + h) * Nn) * Cc;
    const float* xr = g_xr + ((b * Hh + h) * Nn + i0) * Cc;

    // ---- tile loads ----
    if (tid < 32) {
        float a = att[h * Cc + tid];
        w4_s[tid] = 0.4f * a;
        w6_s[tid] = 0.6f * a;
    }
    #pragma unroll
    for (int q8 = 0; q8 < 8; q8++) {
        int idx = q8 * 512 + tid;          // 4096 float4
        int j = idx >> 3, cc = (idx & 7) << 2;
        *(float4*)&xl_s[j * XL_ST + cc] = *(const float4*)&xl[j * Cc + cc];
    }
    if (tid < 256) {
        int j = tid >> 3, cc = (tid & 7) << 2;
        *(float4*)&xr_s[j * Cc + cc] = *(const float4*)&xr[j * Cc + cc];
    }

    // ---- in-register mask: warp w builds words for rows j = 32w..32w+31.
    // Row j's word (bit l = edge j -> i0+l) ends up in lane (j & 31), i.e.
    // exactly thread tid == j keeps its own mask m.
    unsigned m;
    {
        const int* adjb = adj + (b * Nn + w * 32) * Nn + i0 + l;  // row-major, coalesced per row
        #pragma unroll
        for (int r8 = 0; r8 < 4; r8++) {
            int avv[8];
            #pragma unroll
            for (int k = 0; k < 8; k++) avv[k] = adjb[(r8 * 8 + k) * Nn];   // MLP 8
            #pragma unroll
            for (int k = 0; k < 8; k++) {
                const int row = r8 * 8 + k;
                const int j = w * 32 + row;
                unsigned word = __ballot_sync(0xffffffffu, (avv[k] != 0) || (j == i0 + l));
                if (l == row) m = word;
            }
        }
    }
    __syncthreads();

    // ---- Phase 1: p = mask ? exp(e) : 0, j-sliced. Thread owns j = tid ----
    {
        const int j = tid;
        u64 q[16];
        {
            const ulonglong2* qp = (const ulonglong2*)&xl_s[j * XL_ST];
            #pragma unroll
            for (int k = 0; k < 8; k++) { ulonglong2 t = qp[k]; q[2*k] = t.x; q[2*k+1] = t.y; }
        }
        u64 w4r[16];
        {
            const ulonglong2* wp = (const ulonglong2*)w4_s;
            #pragma unroll
            for (int k = 0; k < 8; k++) { ulonglong2 t = wp[k]; w4r[2*k] = t.x; w4r[2*k+1] = t.y; }
        }
        float v;
        {
            const u64* w6p = (const u64*)w6_s;
            u64 va = 0ull, vb = 0ull;
            #pragma unroll
            for (int k = 0; k < 16; k += 2) {
                va = f2fma(w6p[k],   q[k],   va);
                vb = f2fma(w6p[k+1], q[k+1], vb);
            }
            float2 f = f2unpack(f2add(va, vb));
            v = f.x + f.y;
        }
        float* erow = &et_s[j * ET_ST];

        #pragma unroll 2
        for (int ig = 0; ig < 8; ig++) {
            float ev[4];
            #pragma unroll
            for (int ii = 0; ii < 4; ii++) {
                const int i = ig * 4 + ii;
                const ulonglong2* xp = (const ulonglong2*)&xr_s[i * Cc];
                u64 a0 = 0ull, a1 = 0ull, a2 = 0ull, a3 = 0ull;
                #pragma unroll
                for (int k = 0; k < 8; k += 2) {
                    ulonglong2 t0 = xp[k], t1 = xp[k+1];
                    u64 s0 = f2add(t0.x, q[2*k])   & ABSMASK;
                    u64 s1 = f2add(t0.y, q[2*k+1]) & ABSMASK;
                    u64 s2 = f2add(t1.x, q[2*k+2]) & ABSMASK;
                    u64 s3 = f2add(t1.y, q[2*k+3]) & ABSMASK;
                    a0 = f2fma(w4r[2*k],   s0, a0);
                    a1 = f2fma(w4r[2*k+1], s1, a1);
                    a2 = f2fma(w4r[2*k+2], s2, a2);
                    a3 = f2fma(w4r[2*k+3], s3, a3);
                }
                float2 f = f2unpack(f2add(f2add(a0, a1), f2add(a2, a3)));
                float e = f.x + f.y + v;
                ev[ii] = ((m >> i) & 1u) ? __expf(e) : 0.f;
            }
            *(float4*)&erow[ig * 4] = make_float4(ev[0], ev[1], ev[2], ev[3]);
        }
    }
    __syncthreads();

    // ---- Phase 2: row sums only. Warp w owns rows 2w, 2w+1 ----
    #pragma unroll
    for (int rs = 0; rs < 2; rs++) {
        const int r = 2 * w + rs;
        float sum = 0.f;
        #pragma unroll
        for (int k = 0; k < 16; k++)
            sum += et_s[(k * 32 + l) * ET_ST + r];
        #pragma unroll
        for (int off = 16; off > 0; off >>= 1)
            sum += __shfl_xor_sync(0xffffffffu, sum, off);
        if (l == 0) rinv_s[r] = 1.f / sum;
    }
    __syncthreads();

    // ---- Phase D: warp w -> rows 8*(w&3)..+7, j-quarter (w>>2)*128 ----
    {
        const int rbase = 8 * (w & 3);
        const int q4 = w >> 2;
        const int J0 = q4 * 128;
        const int jp = l >> 3, cq = l & 7;
        float acc[8][4];
        #pragma unroll
        for (int rr = 0; rr < 8; rr++)
            #pragma unroll
            for (int k = 0; k < 4; k++) acc[rr][k] = 0.f;

        #pragma unroll 4
        for (int it = 0; it < 32; it++) {
            const int jrow = J0 + it * 4 + jp;
            float4 xv = *(const float4*)&xl_s[jrow * XL_ST + cq * 4];
            float4 p0 = *(const float4*)&et_s[jrow * ET_ST + rbase];
            float4 p1 = *(const float4*)&et_s[jrow * ET_ST + rbase + 4];
            acc[0][0] += p0.x * xv.x; acc[0][1] += p0.x * xv.y;
            acc[0][2] += p0.x * xv.z; acc[0][3] += p0.x * xv.w;
            acc[1][0] += p0.y * xv.x; acc[1][1] += p0.y * xv.y;
            acc[1][2] += p0.y * xv.z; acc[1][3] += p0.y * xv.w;
            acc[2][0] += p0.z * xv.x; acc[2][1] += p0.z * xv.y;
            acc[2][2] += p0.z * xv.z; acc[2][3] += p0.z * xv.w;
            acc[3][0] += p0.w * xv.x; acc[3][1] += p0.w * xv.y;
            acc[3][2] += p0.w * xv.z; acc[3][3] += p0.w * xv.w;
            acc[4][0] += p1.x * xv.x; acc[4][1] += p1.x * xv.y;
            acc[4][2] += p1.x * xv.z; acc[4][3] += p1.x * xv.w;
            acc[5][0] += p1.y * xv.x; acc[5][1] += p1.y * xv.y;
            acc[5][2] += p1.y * xv.z; acc[5][3] += p1.y * xv.w;
            acc[6][0] += p1.z * xv.x; acc[6][1] += p1.z * xv.y;
            acc[6][2] += p1.z * xv.z; acc[6][3] += p1.z * xv.w;
            acc[7][0] += p1.w * xv.x; acc[7][1] += p1.w * xv.y;
            acc[7][2] += p1.w * xv.z; acc[7][3] += p1.w * xv.w;
        }
        // reduce over jp (lane bits 3,4)
        #pragma unroll
        for (int off = 8; off <= 16; off <<= 1)
            #pragma unroll
            for (int rr = 0; rr < 8; rr++)
                #pragma unroll
                for (int k = 0; k < 4; k++)
                    acc[rr][k] += __shfl_xor_sync(0xffffffffu, acc[rr][k], off);

        if (l < 8) {
            #pragma unroll
            for (int rr = 0; rr < 8; rr++)
                *(float4*)&ps_s[(q4 * 32 + rbase + rr) * 32 + cq * 4] =
                    make_float4(acc[rr][0], acc[rr][1], acc[rr][2], acc[rr][3]);
        }
    }
    __syncthreads();

    // ---- combine quarters + scale + bias + store: warp w rows 2w, 2w+1 ----
    {
        const float bv = bias[h * Cc + l];
        #pragma unroll
        for (int rs = 0; rs < 2; rs++) {
            const int r = 2 * w + rs;
            float val = ps_s[r * 32 + l] + ps_s[(32 + r) * 32 + l]
                      + ps_s[(64 + r) * 32 + l] + ps_s[(96 + r) * 32 + l];
            out[(b * Nn + i0 + r) * ODIM + h * Cc + l] = val * rinv_s[r] + bv;
        }
    }
}

// ---------------------------------------------------------------------------
extern "C" void kernel_launch(void* const* d_in, const int* in_sizes, int n_in,
                              void* d_out, int out_size)
{
    const float* x    = (const float*)d_in[0];
    const int*   adj  = (const int*)  d_in[1];
    const float* Wl   = (const float*)d_in[2];
    const float* bl   = (const float*)d_in[3];
    const float* Wr   = (const float*)d_in[4];
    const float* br   = (const float*)d_in[5];
    const float* att  = (const float*)d_in[6];
    const float* bias = (const float*)d_in[7];
    float* out = (float*)d_out;

    cudaFuncSetAttribute(gat_kernel, cudaFuncAttributeMaxDynamicSharedMemorySize, SMEM_BYTES);

    dim3 g1(Bn * Nn / BM, (2 * ODIM) / BN);   // (64, 4)
    proj_kernel<<<g1, 256>>>(x, Wl, bl, Wr, br);

    dim3 g2(Nn / 32, Hh, Bn);                 // (16, 4, 8)
    gat_kernel<<<g2, 512, SMEM_BYTES>>>(adj, att, bias, out);
}

// round 15
// speedup vs baseline: 1.2230x; 1.0004x over previous
#include <cuda_runtime.h>

// ---------------------------------------------------------------------------
// BatchedGAT: B=8, N=512, IN=256, H=4, C=32, OUT=128, LeakyReLU slope 0.2
// K1: projections xl = x@W_l + b_l, xr = x@W_r + b_r  -> [B,H,N,C]
// K2: p_ij = mask ? exp(v_j + sum_c 0.4*att_c*|xr_ic + xl_jc|) : 0
//     (linear xr part cancels in softmax; xl part = v_j; no max-sub needed,
//     e is bounded). Mask built in-register via coalesced row ballots.
//     out = (p @ xl) / rowsum + bias. Scores TRANSPOSED: et_s[j][i].
//     512 threads, 32-row i-tiles; phase D = 8 rows x j-quarter, f32x2.
// ---------------------------------------------------------------------------

#define Bn 8
#define Nn 512
#define INDIM 256
#define Hh 4
#define Cc 32
#define ODIM 128

typedef unsigned long long u64;

__device__ float g_xl[Bn * Hh * Nn * Cc];        // [b][h][j][c]
__device__ float g_xr[Bn * Hh * Nn * Cc];        // [b][h][i][c]

__device__ __forceinline__ u64 f2add(u64 a, u64 b) {
    u64 r; asm("add.rn.f32x2 %0, %1, %2;" : "=l"(r) : "l"(a), "l"(b)); return r;
}
__device__ __forceinline__ u64 f2fma(u64 a, u64 b, u64 c) {
    u64 r; asm("fma.rn.f32x2 %0, %1, %2, %3;" : "=l"(r) : "l"(a), "l"(b), "l"(c)); return r;
}
__device__ __forceinline__ float2 f2unpack(u64 v) {
    float2 r; asm("mov.b64 {%0, %1}, %2;" : "=f"(r.x), "=f"(r.y) : "l"(v)); return r;
}
__device__ __forceinline__ u64 f2dup(float p) {
    u64 r; asm("mov.b64 %0, {%1, %1};" : "=l"(r) : "f"(p)); return r;
}

#define ABSMASK 0x7FFFFFFF7FFFFFFFULL

// ---------------------------------------------------------------------------
// Kernel 1: tiled SIMT GEMM. M=4096, K=256, Ncols=256 (xl | xr)
// ---------------------------------------------------------------------------
#define BM 64
#define BN 64
#define BK 16

__global__ void __launch_bounds__(256) proj_kernel(
    const float* __restrict__ x,
    const float* __restrict__ Wl, const float* __restrict__ bl,
    const float* __restrict__ Wr, const float* __restrict__ br)
{
    __shared__ float As[BK][BM + 4];
    __shared__ float Bs[BK][BN + 4];

    const int tid = threadIdx.x;
    const int m0 = blockIdx.x * BM;
    const int n0 = blockIdx.y * BN;
    const float* W  = (n0 < 128) ? Wl : Wr;
    const float* bb = (n0 < 128) ? bl : br;
    float* dstg     = (n0 < 128) ? g_xl : g_xr;
    const int wcol0 = n0 & 127;

    const int ty = tid >> 4;
    const int tx = tid & 15;
    const int ar  = tid >> 2;
    const int ak4 = (tid & 3) << 2;
    const int bk  = tid >> 4;
    const int bn4 = (tid & 15) << 2;

    float acc[4][4];
    #pragma unroll
    for (int r = 0; r < 4; r++)
        #pragma unroll
        for (int c = 0; c < 4; c++) acc[r][c] = 0.f;

    for (int k0 = 0; k0 < INDIM; k0 += BK) {
        float4 av = *(const float4*)&x[(m0 + ar) * INDIM + k0 + ak4];
        As[ak4 + 0][ar] = av.x;
        As[ak4 + 1][ar] = av.y;
        As[ak4 + 2][ar] = av.z;
        As[ak4 + 3][ar] = av.w;
        float4 bv = *(const float4*)&W[(k0 + bk) * ODIM + wcol0 + bn4];
        *(float4*)&Bs[bk][bn4] = bv;
        __syncthreads();

        #pragma unroll
        for (int kk = 0; kk < BK; kk++) {
            float4 a = *(const float4*)&As[kk][ty * 4];
            float4 b = *(const float4*)&Bs[kk][tx * 4];
            float aa[4] = {a.x, a.y, a.z, a.w};
            float bbv[4] = {b.x, b.y, b.z, b.w};
            #pragma unroll
            for (int r = 0; r < 4; r++)
                #pragma unroll
                for (int c = 0; c < 4; c++) acc[r][c] += aa[r] * bbv[c];
        }
        __syncthreads();
    }

    const int oc0 = n0 + tx * 4;
    const int h   = (oc0 & 127) >> 5;
    const int ch  = oc0 & 31;
    float4 bias4;
    bias4.x = bb[wcol0 + tx * 4 + 0];
    bias4.y = bb[wcol0 + tx * 4 + 1];
    bias4.z = bb[wcol0 + tx * 4 + 2];
    bias4.w = bb[wcol0 + tx * 4 + 3];

    #pragma unroll
    for (int r = 0; r < 4; r++) {
        const int m = m0 + ty * 4 + r;
        const int bidx = m >> 9;
        const int n = m & 511;
        float4 v;
        v.x = acc[r][0] + bias4.x;
        v.y = acc[r][1] + bias4.y;
        v.z = acc[r][2] + bias4.z;
        v.w = acc[r][3] + bias4.w;
        *(float4*)&dstg[(((bidx * Hh + h) * Nn) + n) * Cc + ch] = v;
    }
}

// ---------------------------------------------------------------------------
// Kernel 2: attention. grid (16, 4, 8), 512 threads. Transposed score buf,
// in-register ballot mask, exp fused into phase 1, f32x2 phase D.
// ---------------------------------------------------------------------------
#define XL_ST 36
#define ET_ST 36                           // et_s[j][i], stride 36
#define SM_XL   0                          // 512*36 = 18432
#define SM_XR   (SM_XL + Nn * XL_ST)       // 1024
#define SM_ET   (SM_XR + 1024)             // 512*36 = 18432
#define SM_W4   (SM_ET + Nn * ET_ST)       // 32
#define SM_W6   (SM_W4 + 32)               // 32
#define SM_RINV (SM_W6 + 32)               // 32
#define SM_PS   (SM_RINV + 32)             // 4 quarters * 32 rows * 32 ch = 4096
#define SM_FLOATS (SM_PS + 4096)
#define SMEM_BYTES (SM_FLOATS * 4)         // 168320 bytes

__global__ void __launch_bounds__(512) gat_kernel(
    const int* __restrict__ adj,
    const float* __restrict__ att,
    const float* __restrict__ bias,
    float* __restrict__ out)
{
    extern __shared__ float sm[];
    float* xl_s = sm + SM_XL;
    float* xr_s = sm + SM_XR;
    float* et_s = sm + SM_ET;
    float* w4_s = sm + SM_W4;
    float* w6_s = sm + SM_W6;
    float* rinv_s = sm + SM_RINV;
    float* ps_s = sm + SM_PS;

    const int tid = threadIdx.x;
    const int w = tid >> 5;
    const int l = tid & 31;
    const int b  = blockIdx.z;
    const int h  = blockIdx.y;
    const int bx = blockIdx.x;
    const int i0 = bx * 32;

    const float* xl = g_xl + ((b * Hh + h) * Nn) * Cc;
    const float* xr = g_xr + ((b * Hh + h) * Nn + i0) * Cc;

    // ---- tile loads ----
    if (tid < 32) {
        float a = att[h * Cc + tid];
        w4_s[tid] = 0.4f * a;
        w6_s[tid] = 0.6f * a;
    }
    #pragma unroll
    for (int q8 = 0; q8 < 8; q8++) {
        int idx = q8 * 512 + tid;          // 4096 float4
        int j = idx >> 3, cc = (idx & 7) << 2;
        *(float4*)&xl_s[j * XL_ST + cc] = *(const float4*)&xl[j * Cc + cc];
    }
    if (tid < 256) {
        int j = tid >> 3, cc = (tid & 7) << 2;
        *(float4*)&xr_s[j * Cc + cc] = *(const float4*)&xr[j * Cc + cc];
    }

    // ---- in-register mask: warp w builds words for rows j = 32w..32w+31.
    // Row j's word (bit l = edge j -> i0+l) ends up in lane (j & 31), i.e.
    // exactly thread tid == j keeps its own mask m.
    unsigned m;
    {
        const int* adjb = adj + (b * Nn + w * 32) * Nn + i0 + l;  // row-major, coalesced per row
        #pragma unroll
        for (int r8 = 0; r8 < 4; r8++) {
            int avv[8];
            #pragma unroll
            for (int k = 0; k < 8; k++) avv[k] = adjb[(r8 * 8 + k) * Nn];   // MLP 8
            #pragma unroll
            for (int k = 0; k < 8; k++) {
                const int row = r8 * 8 + k;
                const int j = w * 32 + row;
                unsigned word = __ballot_sync(0xffffffffu, (avv[k] != 0) || (j == i0 + l));
                if (l == row) m = word;
            }
        }
    }
    __syncthreads();

    // ---- Phase 1: p = mask ? exp(e) : 0, j-sliced. Thread owns j = tid ----
    {
        const int j = tid;
        u64 q[16];
        {
            const ulonglong2* qp = (const ulonglong2*)&xl_s[j * XL_ST];
            #pragma unroll
            for (int k = 0; k < 8; k++) { ulonglong2 t = qp[k]; q[2*k] = t.x; q[2*k+1] = t.y; }
        }
        u64 w4r[16];
        {
            const ulonglong2* wp = (const ulonglong2*)w4_s;
            #pragma unroll
            for (int k = 0; k < 8; k++) { ulonglong2 t = wp[k]; w4r[2*k] = t.x; w4r[2*k+1] = t.y; }
        }
        float v;
        {
            const u64* w6p = (const u64*)w6_s;
            u64 va = 0ull, vb = 0ull;
            #pragma unroll
            for (int k = 0; k < 16; k += 2) {
                va = f2fma(w6p[k],   q[k],   va);
                vb = f2fma(w6p[k+1], q[k+1], vb);
            }
            float2 f = f2unpack(f2add(va, vb));
            v = f.x + f.y;
        }
        float* erow = &et_s[j * ET_ST];

        #pragma unroll 2
        for (int ig = 0; ig < 8; ig++) {
            float ev[4];
            #pragma unroll
            for (int ii = 0; ii < 4; ii++) {
                const int i = ig * 4 + ii;
                const ulonglong2* xp = (const ulonglong2*)&xr_s[i * Cc];
                u64 a0 = 0ull, a1 = 0ull, a2 = 0ull, a3 = 0ull;
                #pragma unroll
                for (int k = 0; k < 8; k += 2) {
                    ulonglong2 t0 = xp[k], t1 = xp[k+1];
                    u64 s0 = f2add(t0.x, q[2*k])   & ABSMASK;
                    u64 s1 = f2add(t0.y, q[2*k+1]) & ABSMASK;
                    u64 s2 = f2add(t1.x, q[2*k+2]) & ABSMASK;
                    u64 s3 = f2add(t1.y, q[2*k+3]) & ABSMASK;
                    a0 = f2fma(w4r[2*k],   s0, a0);
                    a1 = f2fma(w4r[2*k+1], s1, a1);
                    a2 = f2fma(w4r[2*k+2], s2, a2);
                    a3 = f2fma(w4r[2*k+3], s3, a3);
                }
                float2 f = f2unpack(f2add(f2add(a0, a1), f2add(a2, a3)));
                float e = f.x + f.y + v;
                ev[ii] = ((m >> i) & 1u) ? __expf(e) : 0.f;
            }
            *(float4*)&erow[ig * 4] = make_float4(ev[0], ev[1], ev[2], ev[3]);
        }
    }
    __syncthreads();

    // ---- Phase 2: row sums only. Warp w owns rows 2w, 2w+1 ----
    #pragma unroll
    for (int rs = 0; rs < 2; rs++) {
        const int r = 2 * w + rs;
        float sum = 0.f;
        #pragma unroll
        for (int k = 0; k < 16; k++)
            sum += et_s[(k * 32 + l) * ET_ST + r];
        #pragma unroll
        for (int off = 16; off > 0; off >>= 1)
            sum += __shfl_xor_sync(0xffffffffu, sum, off);
        if (l == 0) rinv_s[r] = 1.f / sum;
    }
    __syncthreads();

    // ---- Phase D (f32x2): warp w -> rows 8*(w&3)..+7, j-quarter (w>>2)*128 ----
    {
        const int rbase = 8 * (w & 3);
        const int q4 = w >> 2;
        const int J0 = q4 * 128;
        const int jp = l >> 3, cq = l & 7;
        u64 acc[8][2];
        #pragma unroll
        for (int rr = 0; rr < 8; rr++) { acc[rr][0] = 0ull; acc[rr][1] = 0ull; }

        #pragma unroll 4
        for (int it = 0; it < 32; it++) {
            const int jrow = J0 + it * 4 + jp;
            ulonglong2 xv = *(const ulonglong2*)&xl_s[jrow * XL_ST + cq * 4];
            float4 p0 = *(const float4*)&et_s[jrow * ET_ST + rbase];
            float4 p1 = *(const float4*)&et_s[jrow * ET_ST + rbase + 4];
            u64 d;
            d = f2dup(p0.x); acc[0][0] = f2fma(d, xv.x, acc[0][0]); acc[0][1] = f2fma(d, xv.y, acc[0][1]);
            d = f2dup(p0.y); acc[1][0] = f2fma(d, xv.x, acc[1][0]); acc[1][1] = f2fma(d, xv.y, acc[1][1]);
            d = f2dup(p0.z); acc[2][0] = f2fma(d, xv.x, acc[2][0]); acc[2][1] = f2fma(d, xv.y, acc[2][1]);
            d = f2dup(p0.w); acc[3][0] = f2fma(d, xv.x, acc[3][0]); acc[3][1] = f2fma(d, xv.y, acc[3][1]);
            d = f2dup(p1.x); acc[4][0] = f2fma(d, xv.x, acc[4][0]); acc[4][1] = f2fma(d, xv.y, acc[4][1]);
            d = f2dup(p1.y); acc[5][0] = f2fma(d, xv.x, acc[5][0]); acc[5][1] = f2fma(d, xv.y, acc[5][1]);
            d = f2dup(p1.z); acc[6][0] = f2fma(d, xv.x, acc[6][0]); acc[6][1] = f2fma(d, xv.y, acc[6][1]);
            d = f2dup(p1.w); acc[7][0] = f2fma(d, xv.x, acc[7][0]); acc[7][1] = f2fma(d, xv.y, acc[7][1]);
        }
        // unpack, then reduce over jp (lane bits 3,4)
        #pragma unroll
        for (int rr = 0; rr < 8; rr++) {
            float2 lo = f2unpack(acc[rr][0]);
            float2 hi = f2unpack(acc[rr][1]);
            float v0 = lo.x, v1 = lo.y, v2 = hi.x, v3 = hi.y;
            #pragma unroll
            for (int off = 8; off <= 16; off <<= 1) {
                v0 += __shfl_xor_sync(0xffffffffu, v0, off);
                v1 += __shfl_xor_sync(0xffffffffu, v1, off);
                v2 += __shfl_xor_sync(0xffffffffu, v2, off);
                v3 += __shfl_xor_sync(0xffffffffu, v3, off);
            }
            if (l < 8)
                *(float4*)&ps_s[(q4 * 32 + rbase + rr) * 32 + cq * 4] =
                    make_float4(v0, v1, v2, v3);
        }
    }
    __syncthreads();

    // ---- combine quarters + scale + bias + store: warp w rows 2w, 2w+1 ----
    {
        const float bv = bias[h * Cc + l];
        #pragma unroll
        for (int rs = 0; rs < 2; rs++) {
            const int r = 2 * w + rs;
            float val = ps_s[r * 32 + l] + ps_s[(32 + r) * 32 + l]
                      + ps_s[(64 + r) * 32 + l] + ps_s[(96 + r) * 32 + l];
            out[(b * Nn + i0 + r) * ODIM + h * Cc + l] = val * rinv_s[r] + bv;
        }
    }
}

// ---------------------------------------------------------------------------
extern "C" void kernel_launch(void* const* d_in, const int* in_sizes, int n_in,
                              void* d_out, int out_size)
{
    const float* x    = (const float*)d_in[0];
    const int*   adj  = (const int*)  d_in[1];
    const float* Wl   = (const float*)d_in[2];
    const float* bl   = (const float*)d_in[3];
    const float* Wr   = (const float*)d_in[4];
    const float* br   = (const float*)d_in[5];
    const float* att  = (const float*)d_in[6];
    const float* bias = (const float*)d_in[7];
    float* out = (float*)d_out;

    cudaFuncSetAttribute(gat_kernel, cudaFuncAttributeMaxDynamicSharedMemorySize, SMEM_BYTES);

    dim3 g1(Bn * Nn / BM, (2 * ODIM) / BN);   // (64, 4)
    proj_kernel<<<g1, 256>>>(x, Wl, bl, Wr, br);

    dim3 g2(Nn / 32, Hh, Bn);                 // (16, 4, 8)
    gat_kernel<<<g2, 512, SMEM_BYTES>>>(adj, att, bias, out);
}

// round 16
// speedup vs baseline: 1.2268x; 1.0031x over previous
#include <cuda_runtime.h>

// ---------------------------------------------------------------------------
// BatchedGAT: B=8, N=512, IN=256, H=4, C=32, OUT=128, LeakyReLU slope 0.2
// K1: projections xl = x@W_l + b_l, xr = x@W_r + b_r  -> [B,H,N,C]
// K2: p_ij = mask ? exp(v_j + sum_c 0.4*att_c*|xr_ic + xl_jc|) : 0
//     (linear xr part cancels in softmax; xl part = v_j; no max-sub needed,
//     e is bounded). Mask built in-register via coalesced row ballots.
//     out = (p @ xl) / rowsum + bias. Scores TRANSPOSED: et_s[j][i].
//     512 threads, 32-row i-tiles; phase D = 8 rows x j-quarter (scalar).
// ---------------------------------------------------------------------------

#define Bn 8
#define Nn 512
#define INDIM 256
#define Hh 4
#define Cc 32
#define ODIM 128

typedef unsigned long long u64;

__device__ float g_xl[Bn * Hh * Nn * Cc];        // [b][h][j][c]
__device__ float g_xr[Bn * Hh * Nn * Cc];        // [b][h][i][c]

__device__ __forceinline__ u64 f2add(u64 a, u64 b) {
    u64 r; asm("add.rn.f32x2 %0, %1, %2;" : "=l"(r) : "l"(a), "l"(b)); return r;
}
__device__ __forceinline__ u64 f2fma(u64 a, u64 b, u64 c) {
    u64 r; asm("fma.rn.f32x2 %0, %1, %2, %3;" : "=l"(r) : "l"(a), "l"(b), "l"(c)); return r;
}
__device__ __forceinline__ float2 f2unpack(u64 v) {
    float2 r; asm("mov.b64 {%0, %1}, %2;" : "=f"(r.x), "=f"(r.y) : "l"(v)); return r;
}

#define ABSMASK 0x7FFFFFFF7FFFFFFFULL

// ---------------------------------------------------------------------------
// Kernel 1: tiled SIMT GEMM. M=4096, K=256, Ncols=256 (xl | xr)
// ---------------------------------------------------------------------------
#define BM 64
#define BN 64
#define BK 16

__global__ void __launch_bounds__(256) proj_kernel(
    const float* __restrict__ x,
    const float* __restrict__ Wl, const float* __restrict__ bl,
    const float* __restrict__ Wr, const float* __restrict__ br)
{
    __shared__ float As[BK][BM + 4];
    __shared__ float Bs[BK][BN + 4];

    const int tid = threadIdx.x;
    const int m0 = blockIdx.x * BM;
    const int n0 = blockIdx.y * BN;
    const float* W  = (n0 < 128) ? Wl : Wr;
    const float* bb = (n0 < 128) ? bl : br;
    float* dstg     = (n0 < 128) ? g_xl : g_xr;
    const int wcol0 = n0 & 127;

    const int ty = tid >> 4;
    const int tx = tid & 15;
    const int ar  = tid >> 2;
    const int ak4 = (tid & 3) << 2;
    const int bk  = tid >> 4;
    const int bn4 = (tid & 15) << 2;

    float acc[4][4];
    #pragma unroll
    for (int r = 0; r < 4; r++)
        #pragma unroll
        for (int c = 0; c < 4; c++) acc[r][c] = 0.f;

    for (int k0 = 0; k0 < INDIM; k0 += BK) {
        float4 av = *(const float4*)&x[(m0 + ar) * INDIM + k0 + ak4];
        As[ak4 + 0][ar] = av.x;
        As[ak4 + 1][ar] = av.y;
        As[ak4 + 2][ar] = av.z;
        As[ak4 + 3][ar] = av.w;
        float4 bv = *(const float4*)&W[(k0 + bk) * ODIM + wcol0 + bn4];
        *(float4*)&Bs[bk][bn4] = bv;
        __syncthreads();

        #pragma unroll
        for (int kk = 0; kk < BK; kk++) {
            float4 a = *(const float4*)&As[kk][ty * 4];
            float4 b = *(const float4*)&Bs[kk][tx * 4];
            float aa[4] = {a.x, a.y, a.z, a.w};
            float bbv[4] = {b.x, b.y, b.z, b.w};
            #pragma unroll
            for (int r = 0; r < 4; r++)
                #pragma unroll
                for (int c = 0; c < 4; c++) acc[r][c] += aa[r] * bbv[c];
        }
        __syncthreads();
    }

    const int oc0 = n0 + tx * 4;
    const int h   = (oc0 & 127) >> 5;
    const int ch  = oc0 & 31;
    float4 bias4;
    bias4.x = bb[wcol0 + tx * 4 + 0];
    bias4.y = bb[wcol0 + tx * 4 + 1];
    bias4.z = bb[wcol0 + tx * 4 + 2];
    bias4.w = bb[wcol0 + tx * 4 + 3];

    #pragma unroll
    for (int r = 0; r < 4; r++) {
        const int m = m0 + ty * 4 + r;
        const int bidx = m >> 9;
        const int n = m & 511;
        float4 v;
        v.x = acc[r][0] + bias4.x;
        v.y = acc[r][1] + bias4.y;
        v.z = acc[r][2] + bias4.z;
        v.w = acc[r][3] + bias4.w;
        *(float4*)&dstg[(((bidx * Hh + h) * Nn) + n) * Cc + ch] = v;
    }
}

// ---------------------------------------------------------------------------
// Kernel 2: attention. grid (16, 4, 8), 512 threads. Transposed score buf,
// in-register ballot mask, exp fused into phase 1, scalar phase D.
// ---------------------------------------------------------------------------
#define XL_ST 36
#define ET_ST 36                           // et_s[j][i], stride 36
#define SM_XL   0                          // 512*36 = 18432
#define SM_XR   (SM_XL + Nn * XL_ST)       // 1024
#define SM_ET   (SM_XR + 1024)             // 512*36 = 18432
#define SM_W4   (SM_ET + Nn * ET_ST)       // 32
#define SM_W6   (SM_W4 + 32)               // 32
#define SM_RINV (SM_W6 + 32)               // 32
#define SM_PS   (SM_RINV + 32)             // 4 quarters * 32 rows * 32 ch = 4096
#define SM_FLOATS (SM_PS + 4096)
#define SMEM_BYTES (SM_FLOATS * 4)         // 168320 bytes

__global__ void __launch_bounds__(512) gat_kernel(
    const int* __restrict__ adj,
    const float* __restrict__ att,
    const float* __restrict__ bias,
    float* __restrict__ out)
{
    extern __shared__ float sm[];
    float* xl_s = sm + SM_XL;
    float* xr_s = sm + SM_XR;
    float* et_s = sm + SM_ET;
    float* w4_s = sm + SM_W4;
    float* w6_s = sm + SM_W6;
    float* rinv_s = sm + SM_RINV;
    float* ps_s = sm + SM_PS;

    const int tid = threadIdx.x;
    const int w = tid >> 5;
    const int l = tid & 31;
    const int b  = blockIdx.z;
    const int h  = blockIdx.y;
    const int bx = blockIdx.x;
    const int i0 = bx * 32;

    const float* xl = g_xl + ((b * Hh + h) * Nn) * Cc;
    const float* xr = g_xr + ((b * Hh + h) * Nn + i0) * Cc;

    // ---- tile loads ----
    if (tid < 32) {
        float a = att[h * Cc + tid];
        w4_s[tid] = 0.4f * a;
        w6_s[tid] = 0.6f * a;
    }
    #pragma unroll
    for (int q8 = 0; q8 < 8; q8++) {
        int idx = q8 * 512 + tid;          // 4096 float4
        int j = idx >> 3, cc = (idx & 7) << 2;
        *(float4*)&xl_s[j * XL_ST + cc] = *(const float4*)&xl[j * Cc + cc];
    }
    if (tid < 256) {
        int j = tid >> 3, cc = (tid & 7) << 2;
        *(float4*)&xr_s[j * Cc + cc] = *(const float4*)&xr[j * Cc + cc];
    }

    // ---- in-register mask: warp w builds words for rows j = 32w..32w+31.
    // Row j's word (bit l = edge j -> i0+l) ends up in lane (j & 31), i.e.
    // exactly thread tid == j keeps its own mask m.
    unsigned m;
    {
        const int* adjb = adj + (b * Nn + w * 32) * Nn + i0 + l;  // row-major, coalesced per row
        #pragma unroll
        for (int r8 = 0; r8 < 4; r8++) {
            int avv[8];
            #pragma unroll
            for (int k = 0; k < 8; k++) avv[k] = adjb[(r8 * 8 + k) * Nn];   // MLP 8
            #pragma unroll
            for (int k = 0; k < 8; k++) {
                const int row = r8 * 8 + k;
                const int j = w * 32 + row;
                unsigned word = __ballot_sync(0xffffffffu, (avv[k] != 0) || (j == i0 + l));
                if (l == row) m = word;
            }
        }
    }
    __syncthreads();

    // ---- Phase 1: p = mask ? exp(e) : 0, j-sliced. Thread owns j = tid ----
    {
        const int j = tid;
        u64 q[16];
        {
            const ulonglong2* qp = (const ulonglong2*)&xl_s[j * XL_ST];
            #pragma unroll
            for (int k = 0; k < 8; k++) { ulonglong2 t = qp[k]; q[2*k] = t.x; q[2*k+1] = t.y; }
        }
        u64 w4r[16];
        {
            const ulonglong2* wp = (const ulonglong2*)w4_s;
            #pragma unroll
            for (int k = 0; k < 8; k++) { ulonglong2 t = wp[k]; w4r[2*k] = t.x; w4r[2*k+1] = t.y; }
        }
        float v;
        {
            const u64* w6p = (const u64*)w6_s;
            u64 va = 0ull, vb = 0ull;
            #pragma unroll
            for (int k = 0; k < 16; k += 2) {
                va = f2fma(w6p[k],   q[k],   va);
                vb = f2fma(w6p[k+1], q[k+1], vb);
            }
            float2 f = f2unpack(f2add(va, vb));
            v = f.x + f.y;
        }
        float* erow = &et_s[j * ET_ST];

        #pragma unroll 4
        for (int ig = 0; ig < 8; ig++) {
            float ev[4];
            #pragma unroll
            for (int ii = 0; ii < 4; ii++) {
                const int i = ig * 4 + ii;
                const ulonglong2* xp = (const ulonglong2*)&xr_s[i * Cc];
                u64 a0 = 0ull, a1 = 0ull, a2 = 0ull, a3 = 0ull;
                #pragma unroll
                for (int k = 0; k < 8; k += 2) {
                    ulonglong2 t0 = xp[k], t1 = xp[k+1];
                    u64 s0 = f2add(t0.x, q[2*k])   & ABSMASK;
                    u64 s1 = f2add(t0.y, q[2*k+1]) & ABSMASK;
                    u64 s2 = f2add(t1.x, q[2*k+2]) & ABSMASK;
                    u64 s3 = f2add(t1.y, q[2*k+3]) & ABSMASK;
                    a0 = f2fma(w4r[2*k],   s0, a0);
                    a1 = f2fma(w4r[2*k+1], s1, a1);
                    a2 = f2fma(w4r[2*k+2], s2, a2);
                    a3 = f2fma(w4r[2*k+3], s3, a3);
                }
                float2 f = f2unpack(f2add(f2add(a0, a1), f2add(a2, a3)));
                float e = f.x + f.y + v;
                ev[ii] = ((m >> i) & 1u) ? __expf(e) : 0.f;
            }
            *(float4*)&erow[ig * 4] = make_float4(ev[0], ev[1], ev[2], ev[3]);
        }
    }
    __syncthreads();

    // ---- Phase 2: row sums only. Warp w owns rows 2w, 2w+1 ----
    #pragma unroll
    for (int rs = 0; rs < 2; rs++) {
        const int r = 2 * w + rs;
        float sum = 0.f;
        #pragma unroll
        for (int k = 0; k < 16; k++)
            sum += et_s[(k * 32 + l) * ET_ST + r];
        #pragma unroll
        for (int off = 16; off > 0; off >>= 1)
            sum += __shfl_xor_sync(0xffffffffu, sum, off);
        if (l == 0) rinv_s[r] = 1.f / sum;
    }
    __syncthreads();

    // ---- Phase D (scalar): warp w -> rows 8*(w&3)..+7, j-quarter (w>>2)*128 ----
    {
        const int rbase = 8 * (w & 3);
        const int q4 = w >> 2;
        const int J0 = q4 * 128;
        const int jp = l >> 3, cq = l & 7;
        float acc[8][4];
        #pragma unroll
        for (int rr = 0; rr < 8; rr++)
            #pragma unroll
            for (int k = 0; k < 4; k++) acc[rr][k] = 0.f;

        #pragma unroll 4
        for (int it = 0; it < 32; it++) {
            const int jrow = J0 + it * 4 + jp;
            float4 xv = *(const float4*)&xl_s[jrow * XL_ST + cq * 4];
            float4 p0 = *(const float4*)&et_s[jrow * ET_ST + rbase];
            float4 p1 = *(const float4*)&et_s[jrow * ET_ST + rbase + 4];
            acc[0][0] += p0.x * xv.x; acc[0][1] += p0.x * xv.y;
            acc[0][2] += p0.x * xv.z; acc[0][3] += p0.x * xv.w;
            acc[1][0] += p0.y * xv.x; acc[1][1] += p0.y * xv.y;
            acc[1][2] += p0.y * xv.z; acc[1][3] += p0.y * xv.w;
            acc[2][0] += p0.z * xv.x; acc[2][1] += p0.z * xv.y;
            acc[2][2] += p0.z * xv.z; acc[2][3] += p0.z * xv.w;
            acc[3][0] += p0.w * xv.x; acc[3][1] += p0.w * xv.y;
            acc[3][2] += p0.w * xv.z; acc[3][3] += p0.w * xv.w;
            acc[4][0] += p1.x * xv.x; acc[4][1] += p1.x * xv.y;
            acc[4][2] += p1.x * xv.z; acc[4][3] += p1.x * xv.w;
            acc[5][0] += p1.y * xv.x; acc[5][1] += p1.y * xv.y;
            acc[5][2] += p1.y * xv.z; acc[5][3] += p1.y * xv.w;
            acc[6][0] += p1.z * xv.x; acc[6][1] += p1.z * xv.y;
            acc[6][2] += p1.z * xv.z; acc[6][3] += p1.z * xv.w;
            acc[7][0] += p1.w * xv.x; acc[7][1] += p1.w * xv.y;
            acc[7][2] += p1.w * xv.z; acc[7][3] += p1.w * xv.w;
        }
        // reduce over jp (lane bits 3,4)
        #pragma unroll
        for (int off = 8; off <= 16; off <<= 1)
            #pragma unroll
            for (int rr = 0; rr < 8; rr++)
                #pragma unroll
                for (int k = 0; k < 4; k++)
                    acc[rr][k] += __shfl_xor_sync(0xffffffffu, acc[rr][k], off);

        if (l < 8) {
            #pragma unroll
            for (int rr = 0; rr < 8; rr++)
                *(float4*)&ps_s[(q4 * 32 + rbase + rr) * 32 + cq * 4] =
                    make_float4(acc[rr][0], acc[rr][1], acc[rr][2], acc[rr][3]);
        }
    }
    __syncthreads();

    // ---- combine quarters + scale + bias + store: warp w rows 2w, 2w+1 ----
    {
        const float bv = bias[h * Cc + l];
        #pragma unroll
        for (int rs = 0; rs < 2; rs++) {
            const int r = 2 * w + rs;
            float val = ps_s[r * 32 + l] + ps_s[(32 + r) * 32 + l]
                      + ps_s[(64 + r) * 32 + l] + ps_s[(96 + r) * 32 + l];
            out[(b * Nn + i0 + r) * ODIM + h * Cc + l] = val * rinv_s[r] + bv;
        }
    }
}

// ---------------------------------------------------------------------------
extern "C" void kernel_launch(void* const* d_in, const int* in_sizes, int n_in,
                              void* d_out, int out_size)
{
    const float* x    = (const float*)d_in[0];
    const int*   adj  = (const int*)  d_in[1];
    const float* Wl   = (const float*)d_in[2];
    const float* bl   = (const float*)d_in[3];
    const float* Wr   = (const float*)d_in[4];
    const float* br   = (const float*)d_in[5];
    const float* att  = (const float*)d_in[6];
    const float* bias = (const float*)d_in[7];
    float* out = (float*)d_out;

    cudaFuncSetAttribute(gat_kernel, cudaFuncAttributeMaxDynamicSharedMemorySize, SMEM_BYTES);

    dim3 g1(Bn * Nn / BM, (2 * ODIM) / BN);   // (64, 4)
    proj_kernel<<<g1, 256>>>(x, Wl, bl, Wr, br);

    dim3 g2(Nn / 32, Hh, Bn);                 // (16, 4, 8)
    gat_kernel<<<g2, 512, SMEM_BYTES>>>(adj, att, bias, out);
}